// round 2
// baseline (speedup 1.0000x reference)
#include <cuda_runtime.h>
#include <math.h>

// ---------------- problem constants ----------------
#define Bc    8
#define NAc   4096
#define NAAc  1024
#define NPCc  4096
#define Kc    16
#define KNCc  14
#define Gc    32
#define DAc   12
#define Fc    128
#define Dc    128
#define NATOM (Bc*NAc)      // 32768
#define NAAT  (Bc*NAAc)     // 8192
#define MDIM  (Gc*DAc)      // 384

// ---------------- scratch (device globals; no allocations allowed) ----------------
__device__ float g_center[NATOM*3];
__device__ float g_amat[NATOM*DAc];
__device__ float g_masky[NATOM];
__device__ float g_M[(size_t)NATOM*MDIM];   // 48 MB
__device__ float g_y[(size_t)NATOM*Fc];     // 16 MB
__device__ float g_att[(size_t)NATOM*Dc];   // 16 MB
__device__ float g_feat[(size_t)NATOM*Dc];  // 16 MB
__device__ float g_pooled[(size_t)NAAT*Dc]; // 4 MB
__device__ float g_mean[Dc];
__device__ float g_inv[Dc];

// ---------------- K0: per-atom center / masked attributes ----------------
__global__ void k0_prep(const float* __restrict__ pc,
                        const float* __restrict__ mask_atom,
                        const float* __restrict__ attr_table,
                        const int*  __restrict__ frame_idx,
                        const int*  __restrict__ attr_idx)
{
    int t = blockIdx.x * blockDim.x + threadIdx.x;
    if (t >= NATOM) return;
    int b = t / NAc;
    int f1 = frame_idx[t*3 + 1];
    const float* p = pc + ((size_t)b*NPCc + f1)*3;
    g_center[t*3+0] = p[0];
    g_center[t*3+1] = p[1];
    g_center[t*3+2] = p[2];

    int ai = attr_idx[t];
    const float* arow = attr_table + (size_t)ai*DAc;
    float av[DAc];
    bool nz = false;
#pragma unroll
    for (int a = 0; a < DAc; a++) { av[a] = arow[a]; nz = nz || (av[a] != 0.0f); }
    float mattr = nz ? 1.0f : 0.0f;
#pragma unroll
    for (int a = 0; a < DAc; a++) g_amat[(size_t)t*DAc + a] = av[a]*mattr;
    g_masky[t] = mask_atom[t]*mattr;
}

// ---------------- K1: per-atom M[g,a] build (warp per atom, lane = gaussian) ----------------
__global__ void k1_buildM(const float* __restrict__ pc,
                          const int*  __restrict__ frame_idx,
                          const int*  __restrict__ nb_idx,
                          const float* __restrict__ gauss)
{
    int warp = (blockIdx.x * blockDim.x + threadIdx.x) >> 5;
    int lane = threadIdx.x & 31;
    if (warp >= NATOM) return;
    int b = warp / NAc;
    const float* pcb = pc + (size_t)b*NPCc*3;

    int f0 = frame_idx[warp*3+0];
    int f1 = frame_idx[warp*3+1];
    int f2 = frame_idx[warp*3+2];

    float cx = pcb[f1*3+0], cy = pcb[f1*3+1], cz = pcb[f1*3+2];

    float u1x = pcb[f2*3+0]-cx, u1y = pcb[f2*3+1]-cy, u1z = pcb[f2*3+2]-cz;
    float inv = 1.0f/(sqrtf(u1x*u1x+u1y*u1y+u1z*u1z)+1e-8f);
    u1x*=inv; u1y*=inv; u1z*=inv;

    float vx = pcb[f0*3+0]-cx, vy = pcb[f0*3+1]-cy, vz = pcb[f0*3+2]-cz;
    float dt = vx*u1x+vy*u1y+vz*u1z;
    float u2x = vx-dt*u1x, u2y = vy-dt*u1y, u2z = vz-dt*u1z;
    inv = 1.0f/(sqrtf(u2x*u2x+u2y*u2y+u2z*u2z)+1e-8f);
    u2x*=inv; u2y*=inv; u2z*=inv;

    float u3x = u1y*u2z-u1z*u2y;
    float u3y = u1z*u2x-u1x*u2z;
    float u3z = u1x*u2y-u1y*u2x;

    float gcx = gauss[lane*3+0], gcy = gauss[lane*3+1], gcz = gauss[lane*3+2];

    float acc[DAc];
#pragma unroll
    for (int a = 0; a < DAc; a++) acc[a] = 0.0f;

    const int* nb = nb_idx + (size_t)warp*Kc;
#pragma unroll 4
    for (int k = 0; k < Kc; k++) {
        int nbg = b*NAc + nb[k];
        float dx = g_center[nbg*3+0]-cx;
        float dy = g_center[nbg*3+1]-cy;
        float dz = g_center[nbg*3+2]-cz;
        float r1 = u1x*dx+u1y*dy+u1z*dz;
        float r2 = u2x*dx+u2y*dy+u2z*dz;
        float r3 = u3x*dx+u3y*dy+u3z*dz;
        float t1 = r1-gcx, t2 = r2-gcy, t3 = r3-gcz;
        float gk = __expf(-0.5f*(t1*t1+t2*t2+t3*t3));
        const float4* am = (const float4*)(g_amat + (size_t)nbg*DAc);
        float4 A0 = am[0], A1 = am[1], A2 = am[2];
        acc[0]+=gk*A0.x; acc[1]+=gk*A0.y; acc[2]+=gk*A0.z; acc[3]+=gk*A0.w;
        acc[4]+=gk*A1.x; acc[5]+=gk*A1.y; acc[6]+=gk*A1.z; acc[7]+=gk*A1.w;
        acc[8]+=gk*A2.x; acc[9]+=gk*A2.y; acc[10]+=gk*A2.z; acc[11]+=gk*A2.w;
    }
    float4* Mo = (float4*)(g_M + (size_t)warp*MDIM + lane*DAc);
    Mo[0] = make_float4(acc[0],acc[1],acc[2],acc[3]);
    Mo[1] = make_float4(acc[4],acc[5],acc[6],acc[7]);
    Mo[2] = make_float4(acc[8],acc[9],acc[10],acc[11]);
}

// ---------------- tiled GEMM: C[M x 128] = (A[M x K] @ B[K x 128]) * scale * maskrow ----------------
// BM=64, BN=128, BK=32, 256 threads, 4x8 microtile per thread.
__global__ void gemm128(const float* __restrict__ A,
                        const float* __restrict__ Bm,
                        const float* __restrict__ maskrow,
                        float* __restrict__ C,
                        int Kdim, float scale)
{
    const int BM = 64, BN = 128, BK = 32;
    __shared__ float As[BM][BK+1];
    __shared__ float Bs[BK][BN];

    int row0 = blockIdx.x * BM;
    int tid = threadIdx.x;          // 0..255
    int tx = tid & 15;              // 8 cols each
    int ty = tid >> 4;              // 4 rows each

    float acc[4][8];
#pragma unroll
    for (int i = 0; i < 4; i++)
#pragma unroll
        for (int j = 0; j < 8; j++) acc[i][j] = 0.0f;

    for (int kk = 0; kk < Kdim; kk += BK) {
        // load A tile: 64x32 floats = 512 float4 over 256 threads (2 each)
#pragma unroll
        for (int i = 0; i < 2; i++) {
            int li = tid + i*256;
            int r = li >> 3;        // /8
            int c = li & 7;
            float4 v = *(const float4*)(A + (size_t)(row0 + r)*Kdim + kk + c*4);
            As[r][c*4+0] = v.x; As[r][c*4+1] = v.y;
            As[r][c*4+2] = v.z; As[r][c*4+3] = v.w;
        }
        // load B tile: 32x128 floats = 1024 float4 over 256 threads (4 each)
#pragma unroll
        for (int i = 0; i < 4; i++) {
            int li = tid + i*256;
            int r = li >> 5;        // /32
            int c = li & 31;
            *(float4*)&Bs[r][c*4] = *(const float4*)(Bm + (size_t)(kk + r)*BN + c*4);
        }
        __syncthreads();
#pragma unroll
        for (int k = 0; k < BK; k++) {
            float a0 = As[ty*4+0][k];
            float a1 = As[ty*4+1][k];
            float a2 = As[ty*4+2][k];
            float a3 = As[ty*4+3][k];
            float bb[8];
#pragma unroll
            for (int j = 0; j < 8; j++) bb[j] = Bs[k][tx*8+j];
#pragma unroll
            for (int j = 0; j < 8; j++) {
                acc[0][j] += a0*bb[j];
                acc[1][j] += a1*bb[j];
                acc[2][j] += a2*bb[j];
                acc[3][j] += a3*bb[j];
            }
        }
        __syncthreads();
    }
#pragma unroll
    for (int i = 0; i < 4; i++) {
        int r = row0 + ty*4 + i;
        float m = maskrow[r]*scale;
        float4* Cp = (float4*)(C + (size_t)r*BN + tx*8);
        Cp[0] = make_float4(acc[i][0]*m, acc[i][1]*m, acc[i][2]*m, acc[i][3]*m);
        Cp[1] = make_float4(acc[i][4]*m, acc[i][5]*m, acc[i][6]*m, acc[i][7]*m);
    }
}

// ---------------- K4: per-AA masked softmax pooling (block per (b,m), thread per d) --------------
__global__ void k4_pool(const int*  __restrict__ aa_nb_idx,
                        const int*  __restrict__ seq_idx_atom,
                        const int*  __restrict__ seq_idx_aa,
                        const float* __restrict__ mask_aa)
{
    int bm = blockIdx.x;            // 0..NAAT-1
    int b  = bm / NAAc;
    int d  = threadIdx.x;           // 0..127

    __shared__ int   s_ag[KNCc];
    __shared__ float s_gm[KNCc];    // gate * mask_nb
    __shared__ float s_mask[KNCc];

    if (d < KNCc) {
        int nb = aa_nb_idx[(size_t)bm*KNCc + d];
        int ag = b*NAc + nb;
        s_ag[d] = ag;
        float mnb = g_masky[ag];
        s_mask[d] = mnb;
        int sq = seq_idx_atom[ag];
        int sa = seq_idx_aa[bm];
        s_gm[d] = (sq == sa) ? mnb : 0.0f;
    }
    __syncthreads();

    float logit[KNCc];
    float mx = -3.0e38f;
#pragma unroll
    for (int k = 0; k < KNCc; k++) {
        float att = g_att[(size_t)s_ag[k]*Dc + d];
        float l = (s_mask[k] > 0.0f) ? att : -1.0e9f;
        logit[k] = l;
        mx = fmaxf(mx, l);
    }
    float e[KNCc];
    float se = 0.0f;
#pragma unroll
    for (int k = 0; k < KNCc; k++) { e[k] = __expf(logit[k]-mx); se += e[k]; }
    float inv_se = 1.0f/se;
    float w[KNCc];
    float sw = 0.0f;
#pragma unroll
    for (int k = 0; k < KNCc; k++) { w[k] = e[k]*inv_se*s_gm[k]; sw += w[k]; }
    float inv_den = 1.0f/(sw + 1e-8f);
    float pooled = 0.0f;
#pragma unroll
    for (int k = 0; k < KNCc; k++)
        pooled += (w[k]*inv_den) * g_feat[(size_t)s_ag[k]*Dc + d];

    pooled *= mask_aa[bm];
    g_pooled[(size_t)bm*Dc + d] = pooled;
}

// ---------------- K5: masked batch-norm statistics (block per feature d) ----------------
__global__ void k5_stats(const float* __restrict__ mask_aa)
{
    int d = blockIdx.x;             // 0..127
    int tid = threadIdx.x;          // 256
    float s0 = 0.0f, s1 = 0.0f, s2 = 0.0f;
    for (int r = tid; r < NAAT; r += 256) {
        float m = mask_aa[r];
        float p = g_pooled[(size_t)r*Dc + d];
        s0 += m;
        s1 += m*p;
        s2 += m*p*p;
    }
    __shared__ float sh0[256], sh1[256], sh2[256];
    sh0[tid] = s0; sh1[tid] = s1; sh2[tid] = s2;
    __syncthreads();
    for (int s = 128; s > 0; s >>= 1) {
        if (tid < s) {
            sh0[tid] += sh0[tid+s];
            sh1[tid] += sh1[tid+s];
            sh2[tid] += sh2[tid+s];
        }
        __syncthreads();
    }
    if (tid == 0) {
        float n = sh0[0] + 1e-8f;
        float mean = sh1[0]/n;
        float var = (sh2[0] - 2.0f*mean*sh1[0] + mean*mean*sh0[0])/n;
        g_mean[d] = mean;
        g_inv[d]  = rsqrtf(var + 1e-5f);
    }
}

// ---------------- K6: normalize + relu + write outputs ----------------
__global__ void k6_out(const float* __restrict__ gamma,
                       const float* __restrict__ beta,
                       const float* __restrict__ mask_aa,
                       float* __restrict__ out, int out_size)
{
    int idx = blockIdx.x * blockDim.x + threadIdx.x;
    const int total = NAAT*Dc;
    if (idx < total) {
        int d = idx & (Dc-1);
        int r = idx >> 7;
        float p = g_pooled[idx];
        float v = (gamma[d]*(p - g_mean[d])*g_inv[d] + beta[d]) * mask_aa[r];
        out[idx] = fmaxf(v, 0.0f);
    }
    // second tuple element: mask_aa
    if (idx < NAAT && total + idx < out_size) {
        out[total + idx] = mask_aa[idx];
    }
}

// ---------------- launch ----------------
extern "C" void kernel_launch(void* const* d_in, const int* in_sizes, int n_in,
                              void* d_out, int out_size)
{
    const float* point_clouds  = (const float*)d_in[0];
    const float* mask_atom     = (const float*)d_in[1];
    const float* mask_aa       = (const float*)d_in[2];
    const float* attr_table    = (const float*)d_in[3];
    const float* gauss_centers = (const float*)d_in[4];
    const float* W_nem         = (const float*)d_in[5];
    const float* W_att         = (const float*)d_in[6];
    const float* W_feat        = (const float*)d_in[7];
    const float* bn_gamma      = (const float*)d_in[8];
    const float* bn_beta       = (const float*)d_in[9];
    const int*   frame_idx     = (const int*)d_in[10];
    const int*   attr_idx      = (const int*)d_in[11];
    const int*   nb_idx        = (const int*)d_in[12];
    const int*   seq_idx_atom  = (const int*)d_in[13];
    const int*   seq_idx_aa    = (const int*)d_in[14];
    const int*   aa_nb_idx     = (const int*)d_in[15];
    float* out = (float*)d_out;

    float* pM;    cudaGetSymbolAddress((void**)&pM,    g_M);
    float* pY;    cudaGetSymbolAddress((void**)&pY,    g_y);
    float* pAtt;  cudaGetSymbolAddress((void**)&pAtt,  g_att);
    float* pFeat; cudaGetSymbolAddress((void**)&pFeat, g_feat);
    float* pMask; cudaGetSymbolAddress((void**)&pMask, g_masky);

    // K0: per-atom prep
    k0_prep<<<(NATOM+255)/256, 256>>>(point_clouds, mask_atom, attr_table, frame_idx, attr_idx);

    // K1: build M (warp per atom)
    k1_buildM<<<(NATOM*32)/256, 256>>>(point_clouds, frame_idx, nb_idx, gauss_centers);

    // GEMM1: y = (M @ W_nem) / K * mask
    gemm128<<<NATOM/64, 256>>>(pM, W_nem, pMask, pY, MDIM, 1.0f/(float)Kc);

    // GEMM2: att / feat
    gemm128<<<NATOM/64, 256>>>(pY, W_att,  pMask, pAtt,  Fc, 1.0f);
    gemm128<<<NATOM/64, 256>>>(pY, W_feat, pMask, pFeat, Fc, 1.0f);

    // K4: pooled
    k4_pool<<<NAAT, Dc>>>(aa_nb_idx, seq_idx_atom, seq_idx_aa, mask_aa);

    // K5: batch-norm stats
    k5_stats<<<Dc, 256>>>(mask_aa);

    // K6: outputs
    k6_out<<<(NAAT*Dc + 255)/256, 256>>>(bn_gamma, bn_beta, mask_aa, out, out_size);
}

// round 3
// speedup vs baseline: 1.3792x; 1.3792x over previous
#include <cuda_runtime.h>
#include <math.h>

// ---------------- problem constants ----------------
#define Bc    8
#define NAc   4096
#define NAAc  1024
#define NPCc  4096
#define Kc    16
#define KNCc  14
#define Gc    32
#define DAc   12
#define Fc    128
#define Dc    128
#define NATOM (Bc*NAc)      // 32768
#define NAAT  (Bc*NAAc)     // 8192
#define MDIM  (Gc*DAc)      // 384

// ---------------- scratch (device globals; no allocations allowed) ----------------
__device__ float g_center[NATOM*3];
__device__ float g_amat[NATOM*DAc];
__device__ float g_masky[NATOM];
__device__ float g_M[(size_t)NATOM*MDIM];    // 48 MB
__device__ float g_y[(size_t)NATOM*Fc];      // 16 MB
__device__ float g_af[(size_t)NATOM*2*Dc];   // 32 MB  (att | feat per row)
__device__ float g_Wcat[Fc*2*Dc];            // [128][256] = [W_att | W_feat]
__device__ float g_pooled[(size_t)NAAT*Dc];  // 4 MB
__device__ float g_mean[Dc];
__device__ float g_inv[Dc];

// ---------------- K0: per-atom center / masked attributes ----------------
__global__ void k0_prep(const float* __restrict__ pc,
                        const float* __restrict__ mask_atom,
                        const float* __restrict__ attr_table,
                        const int*  __restrict__ frame_idx,
                        const int*  __restrict__ attr_idx)
{
    int t = blockIdx.x * blockDim.x + threadIdx.x;
    if (t >= NATOM) return;
    int b = t / NAc;
    int f1 = frame_idx[t*3 + 1];
    const float* p = pc + ((size_t)b*NPCc + f1)*3;
    g_center[t*3+0] = p[0];
    g_center[t*3+1] = p[1];
    g_center[t*3+2] = p[2];

    int ai = attr_idx[t];
    const float* arow = attr_table + (size_t)ai*DAc;
    float av[DAc];
    bool nz = false;
#pragma unroll
    for (int a = 0; a < DAc; a++) { av[a] = arow[a]; nz = nz || (av[a] != 0.0f); }
    float mattr = nz ? 1.0f : 0.0f;
#pragma unroll
    for (int a = 0; a < DAc; a++) g_amat[(size_t)t*DAc + a] = av[a]*mattr;
    g_masky[t] = mask_atom[t]*mattr;
}

// ---------------- Kw: concat weights  Wcat[f][0:128]=W_att[f], [128:256]=W_feat[f] -------------
__global__ void kW_cat(const float* __restrict__ Watt, const float* __restrict__ Wfeat)
{
    int i = blockIdx.x * blockDim.x + threadIdx.x;   // 0 .. 128*128-1
    int f = i >> 7, c = i & 127;
    g_Wcat[f*256 + c]       = Watt[i];
    g_Wcat[f*256 + 128 + c] = Wfeat[i];
}

// ---------------- K1: per-atom M[g,a] build (warp per atom, lane = gaussian) ----------------
__global__ void k1_buildM(const float* __restrict__ pc,
                          const int*  __restrict__ frame_idx,
                          const int*  __restrict__ nb_idx,
                          const float* __restrict__ gauss)
{
    int warp = (blockIdx.x * blockDim.x + threadIdx.x) >> 5;
    int lane = threadIdx.x & 31;
    if (warp >= NATOM) return;
    int b = warp / NAc;
    const float* pcb = pc + (size_t)b*NPCc*3;

    int f0 = frame_idx[warp*3+0];
    int f1 = frame_idx[warp*3+1];
    int f2 = frame_idx[warp*3+2];

    // preload all 16 neighbor indices with 4 wide loads (MLP)
    const int4* nb4 = (const int4*)(nb_idx + (size_t)warp*Kc);
    int4 n0 = nb4[0], n1 = nb4[1], n2 = nb4[2], n3 = nb4[3];
    int nbi[Kc] = {n0.x,n0.y,n0.z,n0.w, n1.x,n1.y,n1.z,n1.w,
                   n2.x,n2.y,n2.z,n2.w, n3.x,n3.y,n3.z,n3.w};

    float cx = pcb[f1*3+0], cy = pcb[f1*3+1], cz = pcb[f1*3+2];

    float u1x = pcb[f2*3+0]-cx, u1y = pcb[f2*3+1]-cy, u1z = pcb[f2*3+2]-cz;
    float inv = 1.0f/(sqrtf(u1x*u1x+u1y*u1y+u1z*u1z)+1e-8f);
    u1x*=inv; u1y*=inv; u1z*=inv;

    float vx = pcb[f0*3+0]-cx, vy = pcb[f0*3+1]-cy, vz = pcb[f0*3+2]-cz;
    float dt = vx*u1x+vy*u1y+vz*u1z;
    float u2x = vx-dt*u1x, u2y = vy-dt*u1y, u2z = vz-dt*u1z;
    inv = 1.0f/(sqrtf(u2x*u2x+u2y*u2y+u2z*u2z)+1e-8f);
    u2x*=inv; u2y*=inv; u2z*=inv;

    float u3x = u1y*u2z-u1z*u2y;
    float u3y = u1z*u2x-u1x*u2z;
    float u3z = u1x*u2y-u1y*u2x;

    float gcx = gauss[lane*3+0], gcy = gauss[lane*3+1], gcz = gauss[lane*3+2];

    float acc[DAc];
#pragma unroll
    for (int a = 0; a < DAc; a++) acc[a] = 0.0f;

#pragma unroll
    for (int k = 0; k < Kc; k++) {
        int nbg = b*NAc + nbi[k];
        float dx = g_center[nbg*3+0]-cx;
        float dy = g_center[nbg*3+1]-cy;
        float dz = g_center[nbg*3+2]-cz;
        float r1 = u1x*dx+u1y*dy+u1z*dz;
        float r2 = u2x*dx+u2y*dy+u2z*dz;
        float r3 = u3x*dx+u3y*dy+u3z*dz;
        float t1 = r1-gcx, t2 = r2-gcy, t3 = r3-gcz;
        float gk = __expf(-0.5f*(t1*t1+t2*t2+t3*t3));
        const float4* am = (const float4*)(g_amat + (size_t)nbg*DAc);
        float4 A0 = am[0], A1 = am[1], A2 = am[2];
        acc[0]+=gk*A0.x; acc[1]+=gk*A0.y; acc[2]+=gk*A0.z; acc[3]+=gk*A0.w;
        acc[4]+=gk*A1.x; acc[5]+=gk*A1.y; acc[6]+=gk*A1.z; acc[7]+=gk*A1.w;
        acc[8]+=gk*A2.x; acc[9]+=gk*A2.y; acc[10]+=gk*A2.z; acc[11]+=gk*A2.w;
    }
    float4* Mo = (float4*)(g_M + (size_t)warp*MDIM + lane*DAc);
    Mo[0] = make_float4(acc[0],acc[1],acc[2],acc[3]);
    Mo[1] = make_float4(acc[4],acc[5],acc[6],acc[7]);
    Mo[2] = make_float4(acc[8],acc[9],acc[10],acc[11]);
}

// ---------------- SGEMM: C[r, col0+j] = (A[MxK] @ B[KxN])*masky[r]*scale ----------------
// BM=128, BN=128, BK=16, 256 threads, 8x8 microtile, 2 CTAs/SM.
__global__ __launch_bounds__(256, 2)
void gemm_big(const float* __restrict__ A,
              const float* __restrict__ Bm,
              const float* __restrict__ maskrow,
              float* __restrict__ C,
              int Kdim, int ldb, int ldc, float scale)
{
    const int BM = 128, BN = 128, BK = 16;
    __shared__ float As[BK][BM+4];   // transposed A tile; row = k
    __shared__ float Bs[BK][BN];

    int tid  = threadIdx.x;
    int row0 = blockIdx.x * BM;
    int col0 = blockIdx.y * BN;
    int tx = tid & 15;               // 16 col-groups of 8
    int ty = tid >> 4;               // 16 row-groups of 8

    float acc[8][8];
#pragma unroll
    for (int i = 0; i < 8; i++)
#pragma unroll
        for (int j = 0; j < 8; j++) acc[i][j] = 0.0f;

    for (int kk = 0; kk < Kdim; kk += BK) {
        // A tile: 128x16 = 512 float4, 2 per thread, store transposed
#pragma unroll
        for (int i = 0; i < 2; i++) {
            int li = tid + i*256;
            int ar = li >> 2;            // 0..127
            int ac = (li & 3) * 4;       // 0,4,8,12
            float4 v = *(const float4*)(A + (size_t)(row0 + ar)*Kdim + kk + ac);
            As[ac+0][ar] = v.x; As[ac+1][ar] = v.y;
            As[ac+2][ar] = v.z; As[ac+3][ar] = v.w;
        }
        // B tile: 16x128 = 512 float4, 2 per thread, direct
#pragma unroll
        for (int i = 0; i < 2; i++) {
            int li = tid + i*256;
            int br = li >> 5;            // 0..15
            int bc = (li & 31) * 4;      // 0..124
            *(float4*)&Bs[br][bc] = *(const float4*)(Bm + (size_t)(kk + br)*ldb + col0 + bc);
        }
        __syncthreads();
#pragma unroll
        for (int k = 0; k < BK; k++) {
            float a[8], b[8];
            *(float4*)&a[0] = *(const float4*)&As[k][ty*8];
            *(float4*)&a[4] = *(const float4*)&As[k][ty*8+4];
            *(float4*)&b[0] = *(const float4*)&Bs[k][tx*8];
            *(float4*)&b[4] = *(const float4*)&Bs[k][tx*8+4];
#pragma unroll
            for (int i = 0; i < 8; i++)
#pragma unroll
                for (int j = 0; j < 8; j++)
                    acc[i][j] += a[i]*b[j];
        }
        __syncthreads();
    }
#pragma unroll
    for (int i = 0; i < 8; i++) {
        int r = row0 + ty*8 + i;
        float m = maskrow[r]*scale;
        float* Cp = C + (size_t)r*ldc + col0 + tx*8;
        *(float4*)(Cp)   = make_float4(acc[i][0]*m, acc[i][1]*m, acc[i][2]*m, acc[i][3]*m);
        *(float4*)(Cp+4) = make_float4(acc[i][4]*m, acc[i][5]*m, acc[i][6]*m, acc[i][7]*m);
    }
}

// ---------------- K4: per-AA masked softmax pooling (block per (b,m), thread per d) --------------
__global__ void k4_pool(const int*  __restrict__ aa_nb_idx,
                        const int*  __restrict__ seq_idx_atom,
                        const int*  __restrict__ seq_idx_aa,
                        const float* __restrict__ mask_aa)
{
    int bm = blockIdx.x;            // 0..NAAT-1
    int b  = bm / NAAc;
    int d  = threadIdx.x;           // 0..127

    __shared__ int   s_ag[KNCc];
    __shared__ float s_gm[KNCc];    // gate * mask_nb
    __shared__ float s_mask[KNCc];

    if (d < KNCc) {
        int nb = aa_nb_idx[(size_t)bm*KNCc + d];
        int ag = b*NAc + nb;
        s_ag[d] = ag;
        float mnb = g_masky[ag];
        s_mask[d] = mnb;
        int sq = seq_idx_atom[ag];
        int sa = seq_idx_aa[bm];
        s_gm[d] = (sq == sa) ? mnb : 0.0f;
    }
    __syncthreads();

    float logit[KNCc];
    float mx = -3.0e38f;
#pragma unroll
    for (int k = 0; k < KNCc; k++) {
        float att = g_af[(size_t)s_ag[k]*(2*Dc) + d];
        float l = (s_mask[k] > 0.0f) ? att : -1.0e9f;
        logit[k] = l;
        mx = fmaxf(mx, l);
    }
    float e[KNCc];
    float se = 0.0f;
#pragma unroll
    for (int k = 0; k < KNCc; k++) { e[k] = __expf(logit[k]-mx); se += e[k]; }
    float inv_se = 1.0f/se;
    float w[KNCc];
    float sw = 0.0f;
#pragma unroll
    for (int k = 0; k < KNCc; k++) { w[k] = e[k]*inv_se*s_gm[k]; sw += w[k]; }
    float inv_den = 1.0f/(sw + 1e-8f);
    float pooled = 0.0f;
#pragma unroll
    for (int k = 0; k < KNCc; k++)
        pooled += (w[k]*inv_den) * g_af[(size_t)s_ag[k]*(2*Dc) + Dc + d];

    pooled *= mask_aa[bm];
    g_pooled[(size_t)bm*Dc + d] = pooled;
}

// ---------------- K5: masked batch-norm statistics (block per feature d) ----------------
__global__ void k5_stats(const float* __restrict__ mask_aa)
{
    int d = blockIdx.x;             // 0..127
    int tid = threadIdx.x;          // 256
    float s0 = 0.0f, s1 = 0.0f, s2 = 0.0f;
    for (int r = tid; r < NAAT; r += 256) {
        float m = mask_aa[r];
        float p = g_pooled[(size_t)r*Dc + d];
        s0 += m;
        s1 += m*p;
        s2 += m*p*p;
    }
    __shared__ float sh0[256], sh1[256], sh2[256];
    sh0[tid] = s0; sh1[tid] = s1; sh2[tid] = s2;
    __syncthreads();
    for (int s = 128; s > 0; s >>= 1) {
        if (tid < s) {
            sh0[tid] += sh0[tid+s];
            sh1[tid] += sh1[tid+s];
            sh2[tid] += sh2[tid+s];
        }
        __syncthreads();
    }
    if (tid == 0) {
        float n = sh0[0] + 1e-8f;
        float mean = sh1[0]/n;
        float var = (sh2[0] - 2.0f*mean*sh1[0] + mean*mean*sh0[0])/n;
        g_mean[d] = mean;
        g_inv[d]  = rsqrtf(var + 1e-5f);
    }
}

// ---------------- K6: normalize + relu + write outputs ----------------
__global__ void k6_out(const float* __restrict__ gamma,
                       const float* __restrict__ beta,
                       const float* __restrict__ mask_aa,
                       float* __restrict__ out, int out_size)
{
    int idx = blockIdx.x * blockDim.x + threadIdx.x;
    const int total = NAAT*Dc;
    if (idx < total) {
        int d = idx & (Dc-1);
        int r = idx >> 7;
        float p = g_pooled[idx];
        float v = (gamma[d]*(p - g_mean[d])*g_inv[d] + beta[d]) * mask_aa[r];
        out[idx] = fmaxf(v, 0.0f);
    }
    // second tuple element: mask_aa
    if (idx < NAAT && total + idx < out_size) {
        out[total + idx] = mask_aa[idx];
    }
}

// ---------------- launch ----------------
extern "C" void kernel_launch(void* const* d_in, const int* in_sizes, int n_in,
                              void* d_out, int out_size)
{
    const float* point_clouds  = (const float*)d_in[0];
    const float* mask_atom     = (const float*)d_in[1];
    const float* mask_aa       = (const float*)d_in[2];
    const float* attr_table    = (const float*)d_in[3];
    const float* gauss_centers = (const float*)d_in[4];
    const float* W_nem         = (const float*)d_in[5];
    const float* W_att         = (const float*)d_in[6];
    const float* W_feat        = (const float*)d_in[7];
    const float* bn_gamma      = (const float*)d_in[8];
    const float* bn_beta       = (const float*)d_in[9];
    const int*   frame_idx     = (const int*)d_in[10];
    const int*   attr_idx      = (const int*)d_in[11];
    const int*   nb_idx        = (const int*)d_in[12];
    const int*   seq_idx_atom  = (const int*)d_in[13];
    const int*   seq_idx_aa    = (const int*)d_in[14];
    const int*   aa_nb_idx     = (const int*)d_in[15];
    float* out = (float*)d_out;

    float* pM;    cudaGetSymbolAddress((void**)&pM,    g_M);
    float* pY;    cudaGetSymbolAddress((void**)&pY,    g_y);
    float* pAF;   cudaGetSymbolAddress((void**)&pAF,   g_af);
    float* pWcat; cudaGetSymbolAddress((void**)&pWcat, g_Wcat);
    float* pMask; cudaGetSymbolAddress((void**)&pMask, g_masky);

    // K0: per-atom prep (+ weight concat, independent)
    k0_prep<<<(NATOM+255)/256, 256>>>(point_clouds, mask_atom, attr_table, frame_idx, attr_idx);
    kW_cat<<<(Fc*Dc+255)/256, 256>>>(W_att, W_feat);

    // K1: build M (warp per atom)
    k1_buildM<<<(NATOM*32)/256, 256>>>(point_clouds, frame_idx, nb_idx, gauss_centers);

    // GEMM1: y = (M @ W_nem) / K * mask       [32768 x 384] @ [384 x 128]
    {
        dim3 grid(NATOM/128, 1);
        gemm_big<<<grid, 256>>>(pM, W_nem, pMask, pY, MDIM, Fc, Fc, 1.0f/(float)Kc);
    }
    // GEMM2: [att|feat] = (y @ Wcat) * mask   [32768 x 128] @ [128 x 256]
    {
        dim3 grid(NATOM/128, 2);
        gemm_big<<<grid, 256>>>(pY, pWcat, pMask, pAF, Fc, 2*Dc, 2*Dc, 1.0f);
    }

    // K4: pooled
    k4_pool<<<NAAT, Dc>>>(aa_nb_idx, seq_idx_atom, seq_idx_aa, mask_aa);

    // K5: batch-norm stats
    k5_stats<<<Dc, 256>>>(mask_aa);

    // K6: outputs
    k6_out<<<(NAAT*Dc + 255)/256, 256>>>(bn_gamma, bn_beta, mask_aa, out, out_size);
}

// round 4
// speedup vs baseline: 1.4586x; 1.0576x over previous
#include <cuda_runtime.h>
#include <math.h>
#include <stdint.h>

// ---------------- problem constants ----------------
#define Bc    8
#define NAc   4096
#define NAAc  1024
#define NPCc  4096
#define Kc    16
#define KNCc  14
#define Gc    32
#define DAc   12
#define Fc    128
#define Dc    128
#define NATOM (Bc*NAc)      // 32768
#define NAAT  (Bc*NAAc)     // 8192
#define MDIM  (Gc*DAc)      // 384

// ---------------- scratch (device globals; no allocations allowed) ----------------
__device__ float g_center[NATOM*3];
__device__ float g_amat[NATOM*DAc];
__device__ float g_masky[NATOM];
__device__ float g_M[(size_t)NATOM*MDIM];    // 48 MB
__device__ float g_y[(size_t)NATOM*Fc];      // 16 MB
__device__ float g_af[(size_t)NATOM*2*Dc];   // 32 MB  (att | feat per row)
__device__ float g_Wcat[Fc*2*Dc];            // [128][256] = [W_att | W_feat]
__device__ float g_pooled[(size_t)NAAT*Dc];  // 4 MB
__device__ float g_mean[Dc];
__device__ float g_inv[Dc];

// ---------------- helpers: tf32 split ----------------
__device__ __forceinline__ uint32_t f2tf32(float f) {
    uint32_t u;
    asm("cvt.rna.tf32.f32 %0, %1;" : "=r"(u) : "f"(f));
    return u;
}
__device__ __forceinline__ void mma_tf32(float* d, const uint32_t* a, const uint32_t* b) {
    asm("mma.sync.aligned.m16n8k8.row.col.f32.tf32.tf32.f32 "
        "{%0,%1,%2,%3},{%4,%5,%6,%7},{%8,%9},{%0,%1,%2,%3};"
        : "+f"(d[0]), "+f"(d[1]), "+f"(d[2]), "+f"(d[3])
        : "r"(a[0]), "r"(a[1]), "r"(a[2]), "r"(a[3]), "r"(b[0]), "r"(b[1]));
}

// ---------------- K0: per-atom center / masked attributes ----------------
__global__ void k0_prep(const float* __restrict__ pc,
                        const float* __restrict__ mask_atom,
                        const float* __restrict__ attr_table,
                        const int*  __restrict__ frame_idx,
                        const int*  __restrict__ attr_idx)
{
    int t = blockIdx.x * blockDim.x + threadIdx.x;
    if (t >= NATOM) return;
    int b = t / NAc;
    int f1 = frame_idx[t*3 + 1];
    const float* p = pc + ((size_t)b*NPCc + f1)*3;
    g_center[t*3+0] = p[0];
    g_center[t*3+1] = p[1];
    g_center[t*3+2] = p[2];

    int ai = attr_idx[t];
    const float* arow = attr_table + (size_t)ai*DAc;
    float av[DAc];
    bool nz = false;
#pragma unroll
    for (int a = 0; a < DAc; a++) { av[a] = arow[a]; nz = nz || (av[a] != 0.0f); }
    float mattr = nz ? 1.0f : 0.0f;
#pragma unroll
    for (int a = 0; a < DAc; a++) g_amat[(size_t)t*DAc + a] = av[a]*mattr;
    g_masky[t] = mask_atom[t]*mattr;
}

// ---------------- Kw: concat weights ----------------
__global__ void kW_cat(const float* __restrict__ Watt, const float* __restrict__ Wfeat)
{
    int i = blockIdx.x * blockDim.x + threadIdx.x;   // 0 .. 128*128-1
    int f = i >> 7, c = i & 127;
    g_Wcat[f*256 + c]       = Watt[i];
    g_Wcat[f*256 + 128 + c] = Wfeat[i];
}

// ---------------- K1: per-atom M[g,a] build (warp per atom, lane = gaussian) ----------------
__global__ void k1_buildM(const float* __restrict__ pc,
                          const int*  __restrict__ frame_idx,
                          const int*  __restrict__ nb_idx,
                          const float* __restrict__ gauss)
{
    int warp = (blockIdx.x * blockDim.x + threadIdx.x) >> 5;
    int lane = threadIdx.x & 31;
    if (warp >= NATOM) return;
    int b = warp / NAc;
    const float* pcb = pc + (size_t)b*NPCc*3;

    int f0 = frame_idx[warp*3+0];
    int f1 = frame_idx[warp*3+1];
    int f2 = frame_idx[warp*3+2];

    const int4* nb4 = (const int4*)(nb_idx + (size_t)warp*Kc);
    int4 n0 = nb4[0], n1 = nb4[1], n2 = nb4[2], n3 = nb4[3];
    int nbi[Kc] = {n0.x,n0.y,n0.z,n0.w, n1.x,n1.y,n1.z,n1.w,
                   n2.x,n2.y,n2.z,n2.w, n3.x,n3.y,n3.z,n3.w};

    float cx = pcb[f1*3+0], cy = pcb[f1*3+1], cz = pcb[f1*3+2];

    float u1x = pcb[f2*3+0]-cx, u1y = pcb[f2*3+1]-cy, u1z = pcb[f2*3+2]-cz;
    float inv = 1.0f/(sqrtf(u1x*u1x+u1y*u1y+u1z*u1z)+1e-8f);
    u1x*=inv; u1y*=inv; u1z*=inv;

    float vx = pcb[f0*3+0]-cx, vy = pcb[f0*3+1]-cy, vz = pcb[f0*3+2]-cz;
    float dt = vx*u1x+vy*u1y+vz*u1z;
    float u2x = vx-dt*u1x, u2y = vy-dt*u1y, u2z = vz-dt*u1z;
    inv = 1.0f/(sqrtf(u2x*u2x+u2y*u2y+u2z*u2z)+1e-8f);
    u2x*=inv; u2y*=inv; u2z*=inv;

    float u3x = u1y*u2z-u1z*u2y;
    float u3y = u1z*u2x-u1x*u2z;
    float u3z = u1x*u2y-u1y*u2x;

    float gcx = gauss[lane*3+0], gcy = gauss[lane*3+1], gcz = gauss[lane*3+2];

    float acc[DAc];
#pragma unroll
    for (int a = 0; a < DAc; a++) acc[a] = 0.0f;

#pragma unroll
    for (int k = 0; k < Kc; k++) {
        int nbg = b*NAc + nbi[k];
        float dx = g_center[nbg*3+0]-cx;
        float dy = g_center[nbg*3+1]-cy;
        float dz = g_center[nbg*3+2]-cz;
        float r1 = u1x*dx+u1y*dy+u1z*dz;
        float r2 = u2x*dx+u2y*dy+u2z*dz;
        float r3 = u3x*dx+u3y*dy+u3z*dz;
        float t1 = r1-gcx, t2 = r2-gcy, t3 = r3-gcz;
        float gk = __expf(-0.5f*(t1*t1+t2*t2+t3*t3));
        const float4* am = (const float4*)(g_amat + (size_t)nbg*DAc);
        float4 A0 = am[0], A1 = am[1], A2 = am[2];
        acc[0]+=gk*A0.x; acc[1]+=gk*A0.y; acc[2]+=gk*A0.z; acc[3]+=gk*A0.w;
        acc[4]+=gk*A1.x; acc[5]+=gk*A1.y; acc[6]+=gk*A1.z; acc[7]+=gk*A1.w;
        acc[8]+=gk*A2.x; acc[9]+=gk*A2.y; acc[10]+=gk*A2.z; acc[11]+=gk*A2.w;
    }
    float4* Mo = (float4*)(g_M + (size_t)warp*MDIM + lane*DAc);
    Mo[0] = make_float4(acc[0],acc[1],acc[2],acc[3]);
    Mo[1] = make_float4(acc[4],acc[5],acc[6],acc[7]);
    Mo[2] = make_float4(acc[8],acc[9],acc[10],acc[11]);
}

// ---------------- Tensor-core GEMM (3xTF32): C = (A@B)*masky[r]*scale ----------------
// BM=128, BN=128, BK=16, 256 threads = 8 warps (2m x 4n), warp tile 64x32.
// Smem leading dim 136 (== 8 mod 32) -> conflict-free fragment fetches.
#define LDs 136
__global__ __launch_bounds__(256, 2)
void gemm_tc(const float* __restrict__ A,
             const float* __restrict__ Bm,
             const float* __restrict__ maskrow,
             float* __restrict__ C,
             int Kdim, int ldb, int ldc, float scale)
{
    const int BM = 128, BK = 16;
    __shared__ uint32_t Ah[BK][LDs], Al[BK][LDs];
    __shared__ uint32_t Bh[BK][LDs], Bl[BK][LDs];

    int tid  = threadIdx.x;
    int lane = tid & 31;
    int wid  = tid >> 5;
    int warp_m = wid >> 2;          // 0..1 -> m offset 0/64
    int warp_n = wid & 3;           // 0..3 -> n offset 0/32/64/96
    int row0 = blockIdx.x * BM;
    int col0 = blockIdx.y * 128;

    int r4 = lane >> 2;             // 0..7
    int c4 = lane & 3;              // 0..3

    float acc[4][4][4];
#pragma unroll
    for (int i = 0; i < 4; i++)
#pragma unroll
        for (int j = 0; j < 4; j++)
#pragma unroll
            for (int e = 0; e < 4; e++) acc[i][j][e] = 0.0f;

    for (int kk = 0; kk < Kdim; kk += BK) {
        // A tile: 128 rows x 16 k = 512 float4, 2 per thread; store transposed + split
#pragma unroll
        for (int i = 0; i < 2; i++) {
            int li = tid + i*256;
            int ar = li >> 2;            // 0..127
            int ac = (li & 3) * 4;       // 0,4,8,12
            float4 v = *(const float4*)(A + (size_t)(row0 + ar)*Kdim + kk + ac);
            float f[4] = {v.x, v.y, v.z, v.w};
#pragma unroll
            for (int e = 0; e < 4; e++) {
                uint32_t h = f2tf32(f[e]);
                Ah[ac+e][ar] = h;
                Al[ac+e][ar] = f2tf32(f[e] - __uint_as_float(h));
            }
        }
        // B tile: 16 rows x 128 cols = 512 float4, 2 per thread
#pragma unroll
        for (int i = 0; i < 2; i++) {
            int li = tid + i*256;
            int br = li >> 5;            // 0..15
            int bc = (li & 31) * 4;      // 0..124
            float4 v = *(const float4*)(Bm + (size_t)(kk + br)*ldb + col0 + bc);
            float f[4] = {v.x, v.y, v.z, v.w};
#pragma unroll
            for (int e = 0; e < 4; e++) {
                uint32_t h = f2tf32(f[e]);
                Bh[br][bc+e] = h;
                Bl[br][bc+e] = f2tf32(f[e] - __uint_as_float(h));
            }
        }
        __syncthreads();

#pragma unroll
        for (int ks = 0; ks < BK; ks += 8) {
            int kc = ks + c4;
            // B fragments for all 4 n-subtiles (hi+lo)
            uint32_t bh[4][2], bl[4][2];
#pragma unroll
            for (int j = 0; j < 4; j++) {
                int n = warp_n*32 + j*8 + r4;
                bh[j][0] = Bh[kc][n];   bh[j][1] = Bh[kc+4][n];
                bl[j][0] = Bl[kc][n];   bl[j][1] = Bl[kc+4][n];
            }
#pragma unroll
            for (int i = 0; i < 4; i++) {
                int m = warp_m*64 + i*16 + r4;
                uint32_t ah[4], al[4];
                ah[0] = Ah[kc][m];   ah[1] = Ah[kc][m+8];
                ah[2] = Ah[kc+4][m]; ah[3] = Ah[kc+4][m+8];
                al[0] = Al[kc][m];   al[1] = Al[kc][m+8];
                al[2] = Al[kc+4][m]; al[3] = Al[kc+4][m+8];
#pragma unroll
                for (int j = 0; j < 4; j++) {
                    mma_tf32(acc[i][j], ah, bh[j]);   // Ah*Bh
                    mma_tf32(acc[i][j], ah, bl[j]);   // Ah*Bl
                    mma_tf32(acc[i][j], al, bh[j]);   // Al*Bh
                }
            }
        }
        __syncthreads();
    }

    // epilogue: rows rlo = .. + r4, rhi = rlo + 8; cols base + 2*c4
#pragma unroll
    for (int i = 0; i < 4; i++) {
        int rlo = row0 + warp_m*64 + i*16 + r4;
        float mlo = maskrow[rlo]   * scale;
        float mhi = maskrow[rlo+8] * scale;
#pragma unroll
        for (int j = 0; j < 4; j++) {
            int c = col0 + warp_n*32 + j*8 + c4*2;
            *(float2*)(C + (size_t)rlo*ldc + c)     = make_float2(acc[i][j][0]*mlo, acc[i][j][1]*mlo);
            *(float2*)(C + (size_t)(rlo+8)*ldc + c) = make_float2(acc[i][j][2]*mhi, acc[i][j][3]*mhi);
        }
    }
}

// ---------------- K4: per-AA masked softmax pooling ----------------
__global__ void k4_pool(const int*  __restrict__ aa_nb_idx,
                        const int*  __restrict__ seq_idx_atom,
                        const int*  __restrict__ seq_idx_aa,
                        const float* __restrict__ mask_aa)
{
    int bm = blockIdx.x;            // 0..NAAT-1
    int b  = bm / NAAc;
    int d  = threadIdx.x;           // 0..127

    __shared__ int   s_ag[KNCc];
    __shared__ float s_gm[KNCc];
    __shared__ float s_mask[KNCc];

    if (d < KNCc) {
        int nb = aa_nb_idx[(size_t)bm*KNCc + d];
        int ag = b*NAc + nb;
        s_ag[d] = ag;
        float mnb = g_masky[ag];
        s_mask[d] = mnb;
        int sq = seq_idx_atom[ag];
        int sa = seq_idx_aa[bm];
        s_gm[d] = (sq == sa) ? mnb : 0.0f;
    }
    __syncthreads();

    float logit[KNCc];
    float mx = -3.0e38f;
#pragma unroll
    for (int k = 0; k < KNCc; k++) {
        float att = g_af[(size_t)s_ag[k]*(2*Dc) + d];
        float l = (s_mask[k] > 0.0f) ? att : -1.0e9f;
        logit[k] = l;
        mx = fmaxf(mx, l);
    }
    float e[KNCc];
    float se = 0.0f;
#pragma unroll
    for (int k = 0; k < KNCc; k++) { e[k] = __expf(logit[k]-mx); se += e[k]; }
    float inv_se = 1.0f/se;
    float w[KNCc];
    float sw = 0.0f;
#pragma unroll
    for (int k = 0; k < KNCc; k++) { w[k] = e[k]*inv_se*s_gm[k]; sw += w[k]; }
    float inv_den = 1.0f/(sw + 1e-8f);
    float pooled = 0.0f;
#pragma unroll
    for (int k = 0; k < KNCc; k++)
        pooled += (w[k]*inv_den) * g_af[(size_t)s_ag[k]*(2*Dc) + Dc + d];

    pooled *= mask_aa[bm];
    g_pooled[(size_t)bm*Dc + d] = pooled;
}

// ---------------- K5: masked batch-norm statistics ----------------
__global__ void k5_stats(const float* __restrict__ mask_aa)
{
    int d = blockIdx.x;             // 0..127
    int tid = threadIdx.x;          // 256
    float s0 = 0.0f, s1 = 0.0f, s2 = 0.0f;
    for (int r = tid; r < NAAT; r += 256) {
        float m = mask_aa[r];
        float p = g_pooled[(size_t)r*Dc + d];
        s0 += m;
        s1 += m*p;
        s2 += m*p*p;
    }
    __shared__ float sh0[256], sh1[256], sh2[256];
    sh0[tid] = s0; sh1[tid] = s1; sh2[tid] = s2;
    __syncthreads();
    for (int s = 128; s > 0; s >>= 1) {
        if (tid < s) {
            sh0[tid] += sh0[tid+s];
            sh1[tid] += sh1[tid+s];
            sh2[tid] += sh2[tid+s];
        }
        __syncthreads();
    }
    if (tid == 0) {
        float n = sh0[0] + 1e-8f;
        float mean = sh1[0]/n;
        float var = (sh2[0] - 2.0f*mean*sh1[0] + mean*mean*sh0[0])/n;
        g_mean[d] = mean;
        g_inv[d]  = rsqrtf(var + 1e-5f);
    }
}

// ---------------- K6: normalize + relu + write outputs ----------------
__global__ void k6_out(const float* __restrict__ gamma,
                       const float* __restrict__ beta,
                       const float* __restrict__ mask_aa,
                       float* __restrict__ out, int out_size)
{
    int idx = blockIdx.x * blockDim.x + threadIdx.x;
    const int total = NAAT*Dc;
    if (idx < total) {
        int d = idx & (Dc-1);
        int r = idx >> 7;
        float p = g_pooled[idx];
        float v = (gamma[d]*(p - g_mean[d])*g_inv[d] + beta[d]) * mask_aa[r];
        out[idx] = fmaxf(v, 0.0f);
    }
    if (idx < NAAT && total + idx < out_size) {
        out[total + idx] = mask_aa[idx];
    }
}

// ---------------- launch ----------------
extern "C" void kernel_launch(void* const* d_in, const int* in_sizes, int n_in,
                              void* d_out, int out_size)
{
    const float* point_clouds  = (const float*)d_in[0];
    const float* mask_atom     = (const float*)d_in[1];
    const float* mask_aa       = (const float*)d_in[2];
    const float* attr_table    = (const float*)d_in[3];
    const float* gauss_centers = (const float*)d_in[4];
    const float* W_nem         = (const float*)d_in[5];
    const float* W_att         = (const float*)d_in[6];
    const float* W_feat        = (const float*)d_in[7];
    const float* bn_gamma      = (const float*)d_in[8];
    const float* bn_beta       = (const float*)d_in[9];
    const int*   frame_idx     = (const int*)d_in[10];
    const int*   attr_idx      = (const int*)d_in[11];
    const int*   nb_idx        = (const int*)d_in[12];
    const int*   seq_idx_atom  = (const int*)d_in[13];
    const int*   seq_idx_aa    = (const int*)d_in[14];
    const int*   aa_nb_idx     = (const int*)d_in[15];
    float* out = (float*)d_out;

    float* pM;    cudaGetSymbolAddress((void**)&pM,    g_M);
    float* pY;    cudaGetSymbolAddress((void**)&pY,    g_y);
    float* pAF;   cudaGetSymbolAddress((void**)&pAF,   g_af);
    float* pWcat; cudaGetSymbolAddress((void**)&pWcat, g_Wcat);
    float* pMask; cudaGetSymbolAddress((void**)&pMask, g_masky);

    // K0: per-atom prep (+ weight concat, independent)
    k0_prep<<<(NATOM+255)/256, 256>>>(point_clouds, mask_atom, attr_table, frame_idx, attr_idx);
    kW_cat<<<(Fc*Dc+255)/256, 256>>>(W_att, W_feat);

    // K1: build M (warp per atom)
    k1_buildM<<<(NATOM*32)/256, 256>>>(point_clouds, frame_idx, nb_idx, gauss_centers);

    // GEMM1: y = (M @ W_nem) / K * mask       [32768 x 384] @ [384 x 128]
    {
        dim3 grid(NATOM/128, 1);
        gemm_tc<<<grid, 256>>>(pM, W_nem, pMask, pY, MDIM, Fc, Fc, 1.0f/(float)Kc);
    }
    // GEMM2: [att|feat] = (y @ Wcat) * mask   [32768 x 128] @ [128 x 256]
    {
        dim3 grid(NATOM/128, 2);
        gemm_tc<<<grid, 256>>>(pY, pWcat, pMask, pAF, Fc, 2*Dc, 2*Dc, 1.0f);
    }

    // K4: pooled
    k4_pool<<<NAAT, Dc>>>(aa_nb_idx, seq_idx_atom, seq_idx_aa, mask_aa);

    // K5: batch-norm stats
    k5_stats<<<Dc, 256>>>(mask_aa);

    // K6: outputs
    k6_out<<<(NAAT*Dc + 255)/256, 256>>>(bn_gamma, bn_beta, mask_aa, out, out_size);
}

// round 6
// speedup vs baseline: 1.9906x; 1.3648x over previous
#include <cuda_runtime.h>
#include <cuda_bf16.h>
#include <math.h>
#include <stdint.h>

// ---------------- problem constants ----------------
#define Bc    8
#define NAc   4096
#define NAAc  1024
#define NPCc  4096
#define Kc    16
#define KNCc  14
#define Gc    32
#define DAc   12
#define Fc    128
#define Dc    128
#define NATOM (Bc*NAc)      // 32768
#define NAAT  (Bc*NAAc)     // 8192
#define MDIM  (Gc*DAc)      // 384

// ---------------- scratch (device globals; no allocations allowed) ----------------
__device__ float g_center[NATOM*3];
__device__ float g_amat[NATOM*DAc];
__device__ float g_masky[NATOM];
__device__ float g_M[(size_t)NATOM*MDIM];    // 48 MB
__device__ float g_y[(size_t)NATOM*Fc];      // 16 MB
__device__ float g_af[(size_t)NATOM*2*Dc];   // 32 MB  (att | feat per row)
__device__ float g_Wcat[Fc*2*Dc];            // [128][256] = [W_att | W_feat]
__device__ float g_pooled[(size_t)NAAT*Dc];  // 4 MB
__device__ float g_mean[Dc];
__device__ float g_inv[Dc];

// ---------------- helpers: bf16 split + mma ----------------
__device__ __forceinline__ void split2(float f0, float f1, uint32_t& hi, uint32_t& lo)
{
    __nv_bfloat16 h0 = __float2bfloat16_rn(f0);
    __nv_bfloat16 h1 = __float2bfloat16_rn(f1);
    float r0 = f0 - __bfloat162float(h0);
    float r1 = f1 - __bfloat162float(h1);
    __nv_bfloat16 l0 = __float2bfloat16_rn(r0);
    __nv_bfloat16 l1 = __float2bfloat16_rn(r1);
    hi = ((uint32_t)__bfloat16_as_ushort(h1) << 16) | (uint32_t)__bfloat16_as_ushort(h0);
    lo = ((uint32_t)__bfloat16_as_ushort(l1) << 16) | (uint32_t)__bfloat16_as_ushort(l0);
}
__device__ __forceinline__ void mma_bf16(float* d, const uint32_t* a, const uint32_t* b)
{
    asm("mma.sync.aligned.m16n8k16.row.col.f32.bf16.bf16.f32 "
        "{%0,%1,%2,%3},{%4,%5,%6,%7},{%8,%9},{%0,%1,%2,%3};"
        : "+f"(d[0]), "+f"(d[1]), "+f"(d[2]), "+f"(d[3])
        : "r"(a[0]), "r"(a[1]), "r"(a[2]), "r"(a[3]), "r"(b[0]), "r"(b[1]));
}

// ---------------- K0: per-atom center / masked attributes ----------------
__global__ void k0_prep(const float* __restrict__ pc,
                        const float* __restrict__ mask_atom,
                        const float* __restrict__ attr_table,
                        const int*  __restrict__ frame_idx,
                        const int*  __restrict__ attr_idx)
{
    int t = blockIdx.x * blockDim.x + threadIdx.x;
    if (t >= NATOM) return;
    int b = t / NAc;
    int f1 = frame_idx[t*3 + 1];
    const float* p = pc + ((size_t)b*NPCc + f1)*3;
    g_center[t*3+0] = p[0];
    g_center[t*3+1] = p[1];
    g_center[t*3+2] = p[2];

    int ai = attr_idx[t];
    const float* arow = attr_table + (size_t)ai*DAc;
    float av[DAc];
    bool nz = false;
#pragma unroll
    for (int a = 0; a < DAc; a++) { av[a] = arow[a]; nz = nz || (av[a] != 0.0f); }
    float mattr = nz ? 1.0f : 0.0f;
#pragma unroll
    for (int a = 0; a < DAc; a++) g_amat[(size_t)t*DAc + a] = av[a]*mattr;
    g_masky[t] = mask_atom[t]*mattr;
}

// ---------------- Kw: concat weights ----------------
__global__ void kW_cat(const float* __restrict__ Watt, const float* __restrict__ Wfeat)
{
    int i = blockIdx.x * blockDim.x + threadIdx.x;   // 0 .. 128*128-1
    int f = i >> 7, c = i & 127;
    g_Wcat[f*256 + c]       = Watt[i];
    g_Wcat[f*256 + 128 + c] = Wfeat[i];
}

// ---------------- K1: per-atom M[g,a] build (warp per atom, lane = gaussian) ----------------
__global__ void k1_buildM(const float* __restrict__ pc,
                          const int*  __restrict__ frame_idx,
                          const int*  __restrict__ nb_idx,
                          const float* __restrict__ gauss)
{
    int warp = (blockIdx.x * blockDim.x + threadIdx.x) >> 5;
    int lane = threadIdx.x & 31;
    if (warp >= NATOM) return;
    int b = warp / NAc;
    const float* pcb = pc + (size_t)b*NPCc*3;

    int f0 = frame_idx[warp*3+0];
    int f1 = frame_idx[warp*3+1];
    int f2 = frame_idx[warp*3+2];

    const int4* nb4 = (const int4*)(nb_idx + (size_t)warp*Kc);
    int4 n0 = nb4[0], n1 = nb4[1], n2 = nb4[2], n3 = nb4[3];
    int nbi[Kc] = {n0.x,n0.y,n0.z,n0.w, n1.x,n1.y,n1.z,n1.w,
                   n2.x,n2.y,n2.z,n2.w, n3.x,n3.y,n3.z,n3.w};

    float cx = pcb[f1*3+0], cy = pcb[f1*3+1], cz = pcb[f1*3+2];

    float u1x = pcb[f2*3+0]-cx, u1y = pcb[f2*3+1]-cy, u1z = pcb[f2*3+2]-cz;
    float inv = 1.0f/(sqrtf(u1x*u1x+u1y*u1y+u1z*u1z)+1e-8f);
    u1x*=inv; u1y*=inv; u1z*=inv;

    float vx = pcb[f0*3+0]-cx, vy = pcb[f0*3+1]-cy, vz = pcb[f0*3+2]-cz;
    float dt = vx*u1x+vy*u1y+vz*u1z;
    float u2x = vx-dt*u1x, u2y = vy-dt*u1y, u2z = vz-dt*u1z;
    inv = 1.0f/(sqrtf(u2x*u2x+u2y*u2y+u2z*u2z)+1e-8f);
    u2x*=inv; u2y*=inv; u2z*=inv;

    float u3x = u1y*u2z-u1z*u2y;
    float u3y = u1z*u2x-u1x*u2z;
    float u3z = u1x*u2y-u1y*u2x;

    float gcx = gauss[lane*3+0], gcy = gauss[lane*3+1], gcz = gauss[lane*3+2];

    float acc[DAc];
#pragma unroll
    for (int a = 0; a < DAc; a++) acc[a] = 0.0f;

#pragma unroll
    for (int k = 0; k < Kc; k++) {
        int nbg = b*NAc + nbi[k];
        float dx = g_center[nbg*3+0]-cx;
        float dy = g_center[nbg*3+1]-cy;
        float dz = g_center[nbg*3+2]-cz;
        float r1 = u1x*dx+u1y*dy+u1z*dz;
        float r2 = u2x*dx+u2y*dy+u2z*dz;
        float r3 = u3x*dx+u3y*dy+u3z*dz;
        float t1 = r1-gcx, t2 = r2-gcy, t3 = r3-gcz;
        float gk = __expf(-0.5f*(t1*t1+t2*t2+t3*t3));
        const float4* am = (const float4*)(g_amat + (size_t)nbg*DAc);
        float4 A0 = am[0], A1 = am[1], A2 = am[2];
        acc[0]+=gk*A0.x; acc[1]+=gk*A0.y; acc[2]+=gk*A0.z; acc[3]+=gk*A0.w;
        acc[4]+=gk*A1.x; acc[5]+=gk*A1.y; acc[6]+=gk*A1.z; acc[7]+=gk*A1.w;
        acc[8]+=gk*A2.x; acc[9]+=gk*A2.y; acc[10]+=gk*A2.z; acc[11]+=gk*A2.w;
    }
    float4* Mo = (float4*)(g_M + (size_t)warp*MDIM + lane*DAc);
    Mo[0] = make_float4(acc[0],acc[1],acc[2],acc[3]);
    Mo[1] = make_float4(acc[4],acc[5],acc[6],acc[7]);
    Mo[2] = make_float4(acc[8],acc[9],acc[10],acc[11]);
}

// ---------------- Tensor-core GEMM (bf16x3, m16n8k16): C = (A@B)*masky[r]*scale ----------
// BM=128, BN=128, BK=16 (8 k-pairs), 256 threads = 8 warps (2m x 4n), warp tile 64x32.
// Double-buffered smem with register staging of the next tile's global loads.
#define LDsW 136
__global__ __launch_bounds__(256, 2)
void gemm_tc(const float* __restrict__ A,
             const float* __restrict__ Bm,
             const float* __restrict__ maskrow,
             float* __restrict__ C,
             int Kdim, int ldb, int ldc, float scale)
{
    __shared__ uint32_t Ah2[2][8][LDsW], Al2[2][8][LDsW];
    __shared__ uint32_t Bh2[2][8][LDsW], Bl2[2][8][LDsW];

    int tid  = threadIdx.x;
    int lane = tid & 31;
    int wid  = tid >> 5;
    int warp_m = wid >> 2;          // 0..1 -> m offset 0/64
    int warp_n = wid & 3;           // 0..3 -> n offset 0/32/64/96
    int row0 = blockIdx.x * 128;
    int col0 = blockIdx.y * 128;
    int r4 = lane >> 2;             // 0..7
    int c4 = lane & 3;              // 0..3

    // A fill mapping: two sub-iterations cover 128 rows x 16 k
    int a_r = tid >> 2;             // 0..63 (+64 on 2nd)
    int a_c = (tid & 3) * 4;        // 0,4,8,12
    // B fill mapping: thread owns column b_c, 8 consecutive k rows
    int b_c  = tid & 127;
    int b_kg = tid >> 7;            // 0/1 -> k rows 0..7 / 8..15

    float4 av0, av1;
    float  bv[8];

    float acc[4][4][4];
#pragma unroll
    for (int i = 0; i < 4; i++)
#pragma unroll
        for (int j = 0; j < 4; j++)
#pragma unroll
            for (int e = 0; e < 4; e++) acc[i][j][e] = 0.0f;

    auto load_regs = [&](int kk) {
        av0 = *(const float4*)(A + (size_t)(row0 + a_r)*Kdim + kk + a_c);
        av1 = *(const float4*)(A + (size_t)(row0 + 64 + a_r)*Kdim + kk + a_c);
#pragma unroll
        for (int e = 0; e < 8; e++)
            bv[e] = Bm[(size_t)(kk + b_kg*8 + e)*ldb + col0 + b_c];
    };
    auto store_tile = [&](int buf) {
        int ac2 = a_c >> 1;         // 0,2,4,6
        uint32_t h, l;
        split2(av0.x, av0.y, h, l); Ah2[buf][ac2  ][a_r]    = h; Al2[buf][ac2  ][a_r]    = l;
        split2(av0.z, av0.w, h, l); Ah2[buf][ac2+1][a_r]    = h; Al2[buf][ac2+1][a_r]    = l;
        split2(av1.x, av1.y, h, l); Ah2[buf][ac2  ][a_r+64] = h; Al2[buf][ac2  ][a_r+64] = l;
        split2(av1.z, av1.w, h, l); Ah2[buf][ac2+1][a_r+64] = h; Al2[buf][ac2+1][a_r+64] = l;
#pragma unroll
        for (int p = 0; p < 4; p++) {
            split2(bv[2*p], bv[2*p+1], h, l);
            Bh2[buf][b_kg*4 + p][b_c] = h;
            Bl2[buf][b_kg*4 + p][b_c] = l;
        }
    };

    int T = Kdim >> 4;
    load_regs(0);
    store_tile(0);
    __syncthreads();

    for (int t = 0; t < T; t++) {
        int buf = t & 1;
        if (t + 1 < T) load_regs((t + 1) << 4);

        // B fragments for all 4 n-subtiles (hi+lo)
        uint32_t bh[4][2], bl[4][2];
#pragma unroll
        for (int j = 0; j < 4; j++) {
            int n = warp_n*32 + j*8 + r4;
            bh[j][0] = Bh2[buf][c4  ][n];  bh[j][1] = Bh2[buf][c4+4][n];
            bl[j][0] = Bl2[buf][c4  ][n];  bl[j][1] = Bl2[buf][c4+4][n];
        }
#pragma unroll
        for (int i = 0; i < 4; i++) {
            int m = warp_m*64 + i*16 + r4;
            uint32_t ah[4], al[4];
            ah[0] = Ah2[buf][c4  ][m]; ah[1] = Ah2[buf][c4  ][m+8];
            ah[2] = Ah2[buf][c4+4][m]; ah[3] = Ah2[buf][c4+4][m+8];
            al[0] = Al2[buf][c4  ][m]; al[1] = Al2[buf][c4  ][m+8];
            al[2] = Al2[buf][c4+4][m]; al[3] = Al2[buf][c4+4][m+8];
#pragma unroll
            for (int j = 0; j < 4; j++) {
                mma_bf16(acc[i][j], ah, bh[j]);   // Ah*Bh
                mma_bf16(acc[i][j], ah, bl[j]);   // Ah*Bl
                mma_bf16(acc[i][j], al, bh[j]);   // Al*Bh
            }
        }
        __syncthreads();
        if (t + 1 < T) {
            store_tile((t + 1) & 1);
            __syncthreads();
        }
    }

    // epilogue
#pragma unroll
    for (int i = 0; i < 4; i++) {
        int rlo = row0 + warp_m*64 + i*16 + r4;
        float mlo = maskrow[rlo]   * scale;
        float mhi = maskrow[rlo+8] * scale;
#pragma unroll
        for (int j = 0; j < 4; j++) {
            int c = col0 + warp_n*32 + j*8 + c4*2;
            *(float2*)(C + (size_t)rlo*ldc + c)     = make_float2(acc[i][j][0]*mlo, acc[i][j][1]*mlo);
            *(float2*)(C + (size_t)(rlo+8)*ldc + c) = make_float2(acc[i][j][2]*mhi, acc[i][j][3]*mhi);
        }
    }
}

// ---------------- K4: per-AA masked softmax pooling ----------------
__global__ void k4_pool(const int*  __restrict__ aa_nb_idx,
                        const int*  __restrict__ seq_idx_atom,
                        const int*  __restrict__ seq_idx_aa,
                        const float* __restrict__ mask_aa)
{
    int bm = blockIdx.x;            // 0..NAAT-1
    int b  = bm / NAAc;
    int d  = threadIdx.x;           // 0..127

    __shared__ int   s_ag[KNCc];
    __shared__ float s_gm[KNCc];
    __shared__ float s_mask[KNCc];

    if (d < KNCc) {
        int nb = aa_nb_idx[(size_t)bm*KNCc + d];
        int ag = b*NAc + nb;
        s_ag[d] = ag;
        float mnb = g_masky[ag];
        s_mask[d] = mnb;
        int sq = seq_idx_atom[ag];
        int sa = seq_idx_aa[bm];
        s_gm[d] = (sq == sa) ? mnb : 0.0f;
    }
    __syncthreads();

    float logit[KNCc];
    float mx = -3.0e38f;
#pragma unroll
    for (int k = 0; k < KNCc; k++) {
        float att = g_af[(size_t)s_ag[k]*(2*Dc) + d];
        float l = (s_mask[k] > 0.0f) ? att : -1.0e9f;
        logit[k] = l;
        mx = fmaxf(mx, l);
    }
    float e[KNCc];
    float se = 0.0f;
#pragma unroll
    for (int k = 0; k < KNCc; k++) { e[k] = __expf(logit[k]-mx); se += e[k]; }
    float inv_se = 1.0f/se;
    float w[KNCc];
    float sw = 0.0f;
#pragma unroll
    for (int k = 0; k < KNCc; k++) { w[k] = e[k]*inv_se*s_gm[k]; sw += w[k]; }
    float inv_den = 1.0f/(sw + 1e-8f);
    float pooled = 0.0f;
#pragma unroll
    for (int k = 0; k < KNCc; k++)
        pooled += (w[k]*inv_den) * g_af[(size_t)s_ag[k]*(2*Dc) + Dc + d];

    pooled *= mask_aa[bm];
    g_pooled[(size_t)bm*Dc + d] = pooled;
}

// ---------------- K5: masked batch-norm statistics ----------------
__global__ void k5_stats(const float* __restrict__ mask_aa)
{
    int d = blockIdx.x;             // 0..127
    int tid = threadIdx.x;          // 256
    float s0 = 0.0f, s1 = 0.0f, s2 = 0.0f;
    for (int r = tid; r < NAAT; r += 256) {
        float m = mask_aa[r];
        float p = g_pooled[(size_t)r*Dc + d];
        s0 += m;
        s1 += m*p;
        s2 += m*p*p;
    }
    __shared__ float sh0[256], sh1[256], sh2[256];
    sh0[tid] = s0; sh1[tid] = s1; sh2[tid] = s2;
    __syncthreads();
    for (int s = 128; s > 0; s >>= 1) {
        if (tid < s) {
            sh0[tid] += sh0[tid+s];
            sh1[tid] += sh1[tid+s];
            sh2[tid] += sh2[tid+s];
        }
        __syncthreads();
    }
    if (tid == 0) {
        float n = sh0[0] + 1e-8f;
        float mean = sh1[0]/n;
        float var = (sh2[0] - 2.0f*mean*sh1[0] + mean*mean*sh0[0])/n;
        g_mean[d] = mean;
        g_inv[d]  = rsqrtf(var + 1e-5f);
    }
}

// ---------------- K6: normalize + relu + write outputs ----------------
__global__ void k6_out(const float* __restrict__ gamma,
                       const float* __restrict__ beta,
                       const float* __restrict__ mask_aa,
                       float* __restrict__ out, int out_size)
{
    int idx = blockIdx.x * blockDim.x + threadIdx.x;
    const int total = NAAT*Dc;
    if (idx < total) {
        int d = idx & (Dc-1);
        int r = idx >> 7;
        float p = g_pooled[idx];
        float v = (gamma[d]*(p - g_mean[d])*g_inv[d] + beta[d]) * mask_aa[r];
        out[idx] = fmaxf(v, 0.0f);
    }
    if (idx < NAAT && total + idx < out_size) {
        out[total + idx] = mask_aa[idx];
    }
}

// ---------------- launch ----------------
extern "C" void kernel_launch(void* const* d_in, const int* in_sizes, int n_in,
                              void* d_out, int out_size)
{
    const float* point_clouds  = (const float*)d_in[0];
    const float* mask_atom     = (const float*)d_in[1];
    const float* mask_aa       = (const float*)d_in[2];
    const float* attr_table    = (const float*)d_in[3];
    const float* gauss_centers = (const float*)d_in[4];
    const float* W_nem         = (const float*)d_in[5];
    const float* W_att         = (const float*)d_in[6];
    const float* W_feat        = (const float*)d_in[7];
    const float* bn_gamma      = (const float*)d_in[8];
    const float* bn_beta       = (const float*)d_in[9];
    const int*   frame_idx     = (const int*)d_in[10];
    const int*   attr_idx      = (const int*)d_in[11];
    const int*   nb_idx        = (const int*)d_in[12];
    const int*   seq_idx_atom  = (const int*)d_in[13];
    const int*   seq_idx_aa    = (const int*)d_in[14];
    const int*   aa_nb_idx     = (const int*)d_in[15];
    float* out = (float*)d_out;

    float* pM;    cudaGetSymbolAddress((void**)&pM,    g_M);
    float* pY;    cudaGetSymbolAddress((void**)&pY,    g_y);
    float* pAF;   cudaGetSymbolAddress((void**)&pAF,   g_af);
    float* pWcat; cudaGetSymbolAddress((void**)&pWcat, g_Wcat);
    float* pMask; cudaGetSymbolAddress((void**)&pMask, g_masky);

    // K0: per-atom prep (+ weight concat, independent)
    k0_prep<<<(NATOM+255)/256, 256>>>(point_clouds, mask_atom, attr_table, frame_idx, attr_idx);
    kW_cat<<<(Fc*Dc+255)/256, 256>>>(W_att, W_feat);

    // K1: build M (warp per atom)
    k1_buildM<<<(NATOM*32)/256, 256>>>(point_clouds, frame_idx, nb_idx, gauss_centers);

    // GEMM1: y = (M @ W_nem) / K * mask       [32768 x 384] @ [384 x 128]
    {
        dim3 grid(NATOM/128, 1);
        gemm_tc<<<grid, 256>>>(pM, W_nem, pMask, pY, MDIM, Fc, Fc, 1.0f/(float)Kc);
    }
    // GEMM2: [att|feat] = (y @ Wcat) * mask   [32768 x 128] @ [128 x 256]
    {
        dim3 grid(NATOM/128, 2);
        gemm_tc<<<grid, 256>>>(pY, pWcat, pMask, pAF, Fc, 2*Dc, 2*Dc, 1.0f);
    }

    // K4: pooled
    k4_pool<<<NAAT, Dc>>>(aa_nb_idx, seq_idx_atom, seq_idx_aa, mask_aa);

    // K5: batch-norm stats
    k5_stats<<<Dc, 256>>>(mask_aa);

    // K6: outputs
    k6_out<<<(NAAT*Dc + 255)/256, 256>>>(bn_gamma, bn_beta, mask_aa, out, out_size);
}